// round 13
// baseline (speedup 1.0000x reference)
#include <cuda_runtime.h>

#define IMH 1024
#define IMW 1024
#define NPLANE (IMH*IMW)          // 1048576
#define NTENSOR (4*NPLANE)        // 4194304
#define NTOTAL  (8*NPLANE)        // 8388608
#define BIGV 1e10f
#define GATE 1e30f

// ---- scratch (static device globals; no allocations anywhere) ----
__device__ float g_labA[NTOTAL];
__device__ float g_labB[NTOTAL];
__device__ unsigned int g_minmax[4];            // [img_min, img_max, lab_min, lab_max]
__device__ unsigned int g_bitmap[2][NTENSOR/32];// 2 x 524KB bit sets
__device__ int g_zeroflag[2];
__device__ int g_fgcount;
__device__ int g_cc[2];
// per-tile activity flags, ping-ponged by launch parity. [par][z][by+1][bx+1], 1-ring pad = 0.
// 16 y-tiles + 2 pad = 18 rows, 10 x-tiles + 2 pad = 12 cols.
__device__ unsigned char g_flag[2][8][18][12];

// ------------------------------------------------------------------
__global__ void k_init() {
    int i = blockIdx.x * blockDim.x + threadIdx.x;
    int total = 2 * (NTENSOR / 32);
    unsigned int* bm = &g_bitmap[0][0];
    for (int j = i; j < total; j += gridDim.x * blockDim.x) bm[j] = 0u;
    // flags: parity 0 interior = 1 (launch 0 runs everything), rest = 0
    if (i < 2 * 8 * 18 * 12) {
        int par = i / (8 * 18 * 12), rem = i % (8 * 18 * 12);
        int z = rem / (18 * 12), yy = (rem % (18 * 12)) / 12, xx = rem % 12;
        unsigned char val = (par == 0 && yy >= 1 && yy <= 16 && xx >= 1 && xx <= 10) ? 1 : 0;
        g_flag[par][z][yy][xx] = val;
    }
    if (i == 0) {
        g_minmax[0] = 0xFFFFFFFFu; g_minmax[1] = 0u;
        g_minmax[2] = 0xFFFFFFFFu; g_minmax[3] = 0u;
        g_zeroflag[0] = 0; g_zeroflag[1] = 0;
        g_fgcount = 0;
        g_cc[0] = 0; g_cc[1] = 0;
    }
}

// ---- opening_cross (erosion then dilation, cross SE) + global min/max ----
__global__ __launch_bounds__(1024) void k_open(const float* __restrict__ img,
                                               const float* __restrict__ lab) {
    __shared__ float xs[36][37];
    __shared__ float er[34][35];
    __shared__ float smn[32], smx[32];

    int p = blockIdx.z;
    const float* src = (p < 4) ? (img + p * NPLANE) : (lab + (p - 4) * NPLANE);
    int x0 = blockIdx.x * 32, y0 = blockIdx.y * 32;
    int tx = threadIdx.x, ty = threadIdx.y;
    int tid = ty * 32 + tx;

    for (int i = tid; i < 36 * 36; i += 1024) {
        int yy = i / 36, xx = i % 36;
        int gy = y0 + yy - 2, gx = x0 + xx - 2;
        float v = BIGV;
        if ((unsigned)gy < IMH && (unsigned)gx < IMW) v = src[gy * IMW + gx];
        xs[yy][xx] = v;
    }
    __syncthreads();

    for (int i = tid; i < 34 * 34; i += 1024) {
        int yy = i / 34, xx = i % 34;
        int gy = y0 + yy - 1, gx = x0 + xx - 1;
        float e;
        if ((unsigned)gy < IMH && (unsigned)gx < IMW) {
            e = xs[yy + 1][xx + 1];
            e = fminf(e, xs[yy][xx + 1]);
            e = fminf(e, xs[yy + 2][xx + 1]);
            e = fminf(e, xs[yy + 1][xx]);
            e = fminf(e, xs[yy + 1][xx + 2]);
        } else {
            e = -BIGV;
        }
        er[yy][xx] = e;
    }
    __syncthreads();

    float o = er[ty + 1][tx + 1];
    o = fmaxf(o, er[ty][tx + 1]);
    o = fmaxf(o, er[ty + 2][tx + 1]);
    o = fmaxf(o, er[ty + 1][tx]);
    o = fmaxf(o, er[ty + 1][tx + 2]);
    g_labA[p * NPLANE + (y0 + ty) * IMW + (x0 + tx)] = o;

    float wm = o, wx = o;
    #pragma unroll
    for (int s = 16; s > 0; s >>= 1) {
        wm = fminf(wm, __shfl_xor_sync(0xFFFFFFFFu, wm, s));
        wx = fmaxf(wx, __shfl_xor_sync(0xFFFFFFFFu, wx, s));
    }
    int wid = tid >> 5, lane = tid & 31;
    if (lane == 0) { smn[wid] = wm; smx[wid] = wx; }
    __syncthreads();
    if (wid == 0) {
        wm = smn[lane]; wx = smx[lane];
        #pragma unroll
        for (int s = 16; s > 0; s >>= 1) {
            wm = fminf(wm, __shfl_xor_sync(0xFFFFFFFFu, wm, s));
            wx = fmaxf(wx, __shfl_xor_sync(0xFFFFFFFFu, wx, s));
        }
        if (lane == 0) {
            int t = p >> 2;
            atomicMin(&g_minmax[t * 2 + 0], __float_as_uint(wm));
            atomicMax(&g_minmax[t * 2 + 1], __float_as_uint(wx));
        }
    }
}

// ---- normalize + binarize + init labels (idx+1 for fg, 0 for bg) + fg count ----
__global__ void k_thresh() {
    __shared__ int sred[256];
    int i = blockIdx.x * 256 + threadIdx.x;
    int t = i >> 22;
    float mn = __uint_as_float(g_minmax[t * 2 + 0]);
    float mx = __uint_as_float(g_minmax[t * 2 + 1]);
    float v = g_labA[i];
    float nrm = __fdiv_rn(v - mn, mx - mn + 1e-10f);   // IEEE div, matches XLA
    int m = (nrm >= 0.5f) ? 1 : 0;
    unsigned idx = (unsigned)i & (NTENSOR - 1);
    g_labA[i] = m ? (float)(idx + 1u) : 0.0f;          // shifted labels: fg > 0 always

    int c = (t == 1) ? m : 0;
    sred[threadIdx.x] = c;
    __syncthreads();
    for (int s = 128; s > 0; s >>= 1) {
        if (threadIdx.x < s) sred[threadIdx.x] += sred[threadIdx.x + s];
        __syncthreads();
    }
    if (threadIdx.x == 0 && sred[0]) atomicAdd(&g_fgcount, sred[0]);
}

// ------------------------------------------------------------------
// fused k-iteration masked 3x3-max propagation, register-blocked + tile skipping.
// Tile 128x80, block (16,16)=256 threads, each thread an 8-wide x 5-tall patch.
// Halo 8 -> interior 112x64. __launch_bounds__(256,3): 24 warps/SM.
// Mask implicit: bg px are exactly 0 forever; gate = fmin(nv, v*1e30).
__device__ __forceinline__ int sbase(int ty, int tx) {
    int tid = (ty << 4) + tx;
    return (tid << 3) + ((tid >> 2) << 2);   // 8-word slots + 4 pad per 4-thread group
}
__device__ __forceinline__ void hmax8(const float* s, float L, float R, float* o) {
    o[0] = fmaxf(fmaxf(L, s[0]), s[1]);
    #pragma unroll
    for (int j = 1; j < 7; j++) o[j] = fmaxf(fmaxf(s[j - 1], s[j]), s[j + 1]);
    o[7] = fmaxf(fmaxf(s[6], s[7]), R);
}

#define SXN 2304
#define PH 5                      // rows per thread

__global__ __launch_bounds__(256, 3) void k_prop(int ab, int kIter) {
    __shared__ float sEL[SXN];    // left-edge column, PH rows/thread
    __shared__ float sER[SXN];    // right-edge column
    __shared__ float sTV[SXN];    // top row, 8 cols
    __shared__ float sBV[SXN];    // bottom row
    __shared__ int sRun;

    int tx = threadIdx.x;         // 0..15
    int ty = threadIdx.y;         // 0..15
    int bx = blockIdx.x, by = blockIdx.y, p = blockIdx.z;

    // ---- activity gate: 3x3 neighborhood of prev-launch flags ----
    if (tx == 0 && ty == 0) {
        const unsigned char* f = &g_flag[ab][p][by][bx];  // rows by..by+2, cols bx..bx+2
        int any = 0;
        #pragma unroll
        for (int dy = 0; dy < 3; dy++)
            any |= f[dy * 12 + 0] | f[dy * 12 + 1] | f[dy * 12 + 2];
        sRun = any;
    }
    __syncthreads();
    if (!sRun) {
        if (tx == 0 && ty == 0) g_flag[ab ^ 1][p][by + 1][bx + 1] = 0;
        return;   // buffers already equal here; dst holds current values
    }

    const float* __restrict__ src = ab ? g_labB : g_labA;
    float*       __restrict__ dst = ab ? g_labA : g_labB;

    int gx0 = bx * 112 - 8;
    int gy0 = by * 64 - 8;
    int gxb = gx0 + tx * 8;
    int ry0 = ty * PH;                 // tile-row of this thread's first row
    const float* __restrict__ sp = src + p * NPLANE;

    float v[PH][8];
    bool colOK = ((unsigned)gxb < IMW);
    #pragma unroll
    for (int r = 0; r < PH; r++) {
        int gy = gy0 + ry0 + r;
        if (colOK && (unsigned)gy < IMH) {
            float4 a = *(const float4*)(sp + gy * IMW + gxb);
            float4 b = *(const float4*)(sp + gy * IMW + gxb + 4);
            v[r][0]=a.x; v[r][1]=a.y; v[r][2]=a.z; v[r][3]=a.w;
            v[r][4]=b.x; v[r][5]=b.y; v[r][6]=b.z; v[r][7]=b.w;
        } else {
            #pragma unroll
            for (int j = 0; j < 8; j++) v[r][j] = 0.0f;
        }
    }

    int base = sbase(ty, tx);
    bool changed = false;
    bool tchanged = false;

    for (int it = 0; it < kIter; ++it) {
        if (it > 0) {
            if (!__syncthreads_or((int)changed)) break;
            changed = false;
        }
        // ---- write exchange data ----
        *(float4*)&sEL[base] = make_float4(v[0][0], v[1][0], v[2][0], v[3][0]);
        sEL[base + 4] = v[4][0];
        *(float4*)&sER[base] = make_float4(v[0][7], v[1][7], v[2][7], v[3][7]);
        sER[base + 4] = v[4][7];
        *(float4*)&sTV[base]     = make_float4(v[0][0], v[0][1], v[0][2], v[0][3]);
        *(float4*)&sTV[base + 4] = make_float4(v[0][4], v[0][5], v[0][6], v[0][7]);
        *(float4*)&sBV[base]     = make_float4(v[PH-1][0], v[PH-1][1], v[PH-1][2], v[PH-1][3]);
        *(float4*)&sBV[base + 4] = make_float4(v[PH-1][4], v[PH-1][5], v[PH-1][6], v[PH-1][7]);
        __syncthreads();

        // ---- read neighbors (tile-edge threads are pure halo; 0 is safe) ----
        float vl[PH], vr[PH], up[8], dn[8];
        float upL = 0.f, upR = 0.f, dnL = 0.f, dnR = 0.f;
        if (tx > 0) {
            int b = sbase(ty, tx - 1);
            float4 a = *(const float4*)&sER[b];
            vl[0]=a.x; vl[1]=a.y; vl[2]=a.z; vl[3]=a.w; vl[4]=sER[b + 4];
        } else {
            #pragma unroll
            for (int r = 0; r < PH; r++) vl[r] = 0.f;
        }
        if (tx < 15) {
            int b = sbase(ty, tx + 1);
            float4 a = *(const float4*)&sEL[b];
            vr[0]=a.x; vr[1]=a.y; vr[2]=a.z; vr[3]=a.w; vr[4]=sEL[b + 4];
        } else {
            #pragma unroll
            for (int r = 0; r < PH; r++) vr[r] = 0.f;
        }
        if (ty > 0) {
            int b = sbase(ty - 1, tx);
            float4 a = *(const float4*)&sBV[b], c = *(const float4*)&sBV[b + 4];
            up[0]=a.x; up[1]=a.y; up[2]=a.z; up[3]=a.w; up[4]=c.x; up[5]=c.y; up[6]=c.z; up[7]=c.w;
            if (tx > 0)  upL = sER[sbase(ty - 1, tx - 1) + (PH - 1)];
            if (tx < 15) upR = sEL[sbase(ty - 1, tx + 1) + (PH - 1)];
        } else {
            #pragma unroll
            for (int j = 0; j < 8; j++) up[j] = 0.f;
        }
        if (ty < 15) {
            int b = sbase(ty + 1, tx);
            float4 a = *(const float4*)&sTV[b], c = *(const float4*)&sTV[b + 4];
            dn[0]=a.x; dn[1]=a.y; dn[2]=a.z; dn[3]=a.w; dn[4]=c.x; dn[5]=c.y; dn[6]=c.z; dn[7]=c.w;
            if (tx > 0)  dnL = sER[sbase(ty + 1, tx - 1) + 0];
            if (tx < 15) dnR = sEL[sbase(ty + 1, tx + 1) + 0];
        } else {
            #pragma unroll
            for (int j = 0; j < 8; j++) dn[j] = 0.f;
        }

        // ---- rolling 3-row vertical combine over horizontal maxes (Jacobi) ----
        float rm[3][8];
        float dsum = 0.0f;                      // change detector on fma pipe
        hmax8(up,   upL,   upR,   rm[0]);
        hmax8(v[0], vl[0], vr[0], rm[1]);
        #pragma unroll
        for (int r = 0; r < PH; r++) {
            float* rmN = rm[(r + 2) % 3];
            if (r < PH - 1) hmax8(v[r + 1], vl[r + 1], vr[r + 1], rmN);
            else            hmax8(dn, dnL, dnR, rmN);
            float* rmP = rm[r % 3];
            float* rmC = rm[(r + 1) % 3];
            #pragma unroll
            for (int j = 0; j < 8; j++) {
                float nv = fmaxf(fmaxf(rmP[j], rmC[j]), rmN[j]);
                nv = fminf(nv, v[r][j] * GATE);  // bg (0) stays 0, fg takes nv
                dsum += nv - v[r][j];            // nv >= v, exact (integer-valued floats)
                v[r][j] = nv;
            }
        }
        changed = (dsum > 0.0f);
        tchanged = tchanged || changed;
    }

    // ---- store interior (8-ring halo dropped; per-row predicate) ----
    if (tx >= 1 && tx <= 14 && colOK) {
        float* __restrict__ dp = dst + p * NPLANE;
        #pragma unroll
        for (int r = 0; r < PH; r++) {
            int ry = ry0 + r;
            if (ry >= 8 && ry < 72) {
                int gy = gy0 + ry;
                *(float4*)(dp + gy * IMW + gxb)     = make_float4(v[r][0], v[r][1], v[r][2], v[r][3]);
                *(float4*)(dp + gy * IMW + gxb + 4) = make_float4(v[r][4], v[r][5], v[r][6], v[r][7]);
            }
        }
    }

    // publish activity flag for next launch
    int bc = __syncthreads_or((int)tchanged);
    if (tx == 0 && ty == 0) g_flag[ab ^ 1][p][by + 1][bx + 1] = bc ? 1 : 0;
}

// ---- mark distinct final values: bit[int(label)-1]; zero-flag for 0 ----
// g_labB is valid everywhere: tiles changing in the final launch were written to B;
// all other tiles have A==B (unchanged runs store values equal to their load).
__global__ void k_count() {
    int i = blockIdx.x * 256 + threadIdx.x;
    float v = g_labB[i];
    int t = i >> 22;
    if (v == 0.0f) {
        g_zeroflag[t] = 1;
    } else {
        float vp = __shfl_up_sync(0xFFFFFFFFu, v, 1);
        int lane = threadIdx.x & 31;
        if (lane == 0 || vp != v) {
            unsigned iv = (unsigned)v - 1u;
            atomicOr(&g_bitmap[t][iv >> 5], 1u << (iv & 31));
        }
    }
}

// ---- parallel popcount partial reduction ----
__global__ void k_fin1() {
    __shared__ int s0[256], s1[256];
    int tid = threadIdx.x;
    int c0 = 0, c1 = 0;
    for (int j = blockIdx.x * 256 + tid; j < NTENSOR / 32; j += gridDim.x * 256) {
        c0 += __popc(g_bitmap[0][j]);
        c1 += __popc(g_bitmap[1][j]);
    }
    s0[tid] = c0; s1[tid] = c1;
    __syncthreads();
    for (int s = 128; s > 0; s >>= 1) {
        if (tid < s) { s0[tid] += s0[tid + s]; s1[tid] += s1[tid + s]; }
        __syncthreads();
    }
    if (tid == 0) {
        if (s0[0]) atomicAdd(&g_cc[0], s0[0]);
        if (s1[0]) atomicAdd(&g_cc[1], s1[0]);
    }
}

// ---- emit scalar ----
__global__ void k_fin2(float* out) {
    float ccs  = (float)(g_cc[0] + g_zeroflag[0]);
    float ccsg = (float)(g_cc[1] + g_zeroflag[1]);
    float numSg = (float)g_fgcount;
    out[0] = fabsf(ccsg - ccs) / numSg;
}

// ------------------------------------------------------------------
extern "C" void kernel_launch(void* const* d_in, const int* in_sizes, int n_in,
                              void* d_out, int out_size) {
    const float* img = (const float*)d_in[0];
    const float* lab = (const float*)d_in[1];
    float* out = (float*)d_out;

    k_init<<<256, 256>>>();

    dim3 ob(32, 32), og(32, 32, 8);
    k_open<<<og, ob>>>(img, lab);

    k_thresh<<<NTOTAL / 256, 256>>>();

    dim3 pb(16, 16), pg(10, 16, 8);
    int ab = 0;
    for (int l = 0; l < 19; ++l) {
        int kI = (l < 18) ? 8 : 6;   // 18*8 + 6 = 150 iterations exactly
        k_prop<<<pg, pb>>>(ab, kI);
        ab ^= 1;
    }

    k_count<<<NTOTAL / 256, 256>>>();
    k_fin1<<<256, 256>>>();
    k_fin2<<<1, 1>>>(out);
}

// round 14
// speedup vs baseline: 1.5221x; 1.5221x over previous
#include <cuda_runtime.h>

#define IMH 1024
#define IMW 1024
#define NPLANE (IMH*IMW)          // 1048576
#define NTENSOR (4*NPLANE)        // 4194304
#define NTOTAL  (8*NPLANE)        // 8388608
#define BIGV 1e10f
#define GATE 1e30f

// ---- scratch (static device globals; no allocations anywhere) ----
__device__ float g_labA[NTOTAL];
__device__ float g_labB[NTOTAL];
__device__ unsigned int g_minmax[4];            // [img_min, img_max, lab_min, lab_max]
__device__ unsigned int g_bitmap[2][NTENSOR/32];// 2 x 524KB bit sets
__device__ int g_zeroflag[2];
__device__ int g_fgcount;
__device__ int g_cc[2];
// per-tile activity flags, ping-ponged by launch parity. [par][z][by+1][bx+1], 1-ring pad = 0.
__device__ unsigned char g_flag[2][8][12][12];

// ------------------------------------------------------------------
__global__ void k_init() {
    int i = blockIdx.x * blockDim.x + threadIdx.x;
    int total = 2 * (NTENSOR / 32);
    unsigned int* bm = &g_bitmap[0][0];
    for (int j = i; j < total; j += gridDim.x * blockDim.x) bm[j] = 0u;
    // flags: parity 0 interior = 1 (launch 0 runs everything), rest = 0
    if (i < 2 * 8 * 12 * 12) {
        int par = i / 1152, rem = i % 1152;
        int z = rem / 144, yy = (rem % 144) / 12, xx = rem % 12;
        unsigned char val = (par == 0 && yy >= 1 && yy <= 10 && xx >= 1 && xx <= 10) ? 1 : 0;
        g_flag[par][z][yy][xx] = val;
    }
    if (i == 0) {
        g_minmax[0] = 0xFFFFFFFFu; g_minmax[1] = 0u;
        g_minmax[2] = 0xFFFFFFFFu; g_minmax[3] = 0u;
        g_zeroflag[0] = 0; g_zeroflag[1] = 0;
        g_fgcount = 0;
        g_cc[0] = 0; g_cc[1] = 0;
    }
}

// ---- opening_cross (erosion then dilation, cross SE) + global min/max ----
__global__ __launch_bounds__(1024) void k_open(const float* __restrict__ img,
                                               const float* __restrict__ lab) {
    __shared__ float xs[36][37];
    __shared__ float er[34][35];
    __shared__ float smn[32], smx[32];

    int p = blockIdx.z;
    const float* src = (p < 4) ? (img + p * NPLANE) : (lab + (p - 4) * NPLANE);
    int x0 = blockIdx.x * 32, y0 = blockIdx.y * 32;
    int tx = threadIdx.x, ty = threadIdx.y;
    int tid = ty * 32 + tx;

    for (int i = tid; i < 36 * 36; i += 1024) {
        int yy = i / 36, xx = i % 36;
        int gy = y0 + yy - 2, gx = x0 + xx - 2;
        float v = BIGV;
        if ((unsigned)gy < IMH && (unsigned)gx < IMW) v = src[gy * IMW + gx];
        xs[yy][xx] = v;
    }
    __syncthreads();

    for (int i = tid; i < 34 * 34; i += 1024) {
        int yy = i / 34, xx = i % 34;
        int gy = y0 + yy - 1, gx = x0 + xx - 1;
        float e;
        if ((unsigned)gy < IMH && (unsigned)gx < IMW) {
            e = xs[yy + 1][xx + 1];
            e = fminf(e, xs[yy][xx + 1]);
            e = fminf(e, xs[yy + 2][xx + 1]);
            e = fminf(e, xs[yy + 1][xx]);
            e = fminf(e, xs[yy + 1][xx + 2]);
        } else {
            e = -BIGV;
        }
        er[yy][xx] = e;
    }
    __syncthreads();

    float o = er[ty + 1][tx + 1];
    o = fmaxf(o, er[ty][tx + 1]);
    o = fmaxf(o, er[ty + 2][tx + 1]);
    o = fmaxf(o, er[ty + 1][tx]);
    o = fmaxf(o, er[ty + 1][tx + 2]);
    g_labA[p * NPLANE + (y0 + ty) * IMW + (x0 + tx)] = o;

    float wm = o, wx = o;
    #pragma unroll
    for (int s = 16; s > 0; s >>= 1) {
        wm = fminf(wm, __shfl_xor_sync(0xFFFFFFFFu, wm, s));
        wx = fmaxf(wx, __shfl_xor_sync(0xFFFFFFFFu, wx, s));
    }
    int wid = tid >> 5, lane = tid & 31;
    if (lane == 0) { smn[wid] = wm; smx[wid] = wx; }
    __syncthreads();
    if (wid == 0) {
        wm = smn[lane]; wx = smx[lane];
        #pragma unroll
        for (int s = 16; s > 0; s >>= 1) {
            wm = fminf(wm, __shfl_xor_sync(0xFFFFFFFFu, wm, s));
            wx = fmaxf(wx, __shfl_xor_sync(0xFFFFFFFFu, wx, s));
        }
        if (lane == 0) {
            int t = p >> 2;
            atomicMin(&g_minmax[t * 2 + 0], __float_as_uint(wm));
            atomicMax(&g_minmax[t * 2 + 1], __float_as_uint(wx));
        }
    }
}

// ---- normalize + binarize + init labels (idx+1 for fg, 0 for bg) + fg count ----
__global__ void k_thresh() {
    __shared__ int sred[256];
    int i = blockIdx.x * 256 + threadIdx.x;
    int t = i >> 22;
    float mn = __uint_as_float(g_minmax[t * 2 + 0]);
    float mx = __uint_as_float(g_minmax[t * 2 + 1]);
    float v = g_labA[i];
    float nrm = __fdiv_rn(v - mn, mx - mn + 1e-10f);   // IEEE div, matches XLA
    int m = (nrm >= 0.5f) ? 1 : 0;
    unsigned idx = (unsigned)i & (NTENSOR - 1);
    g_labA[i] = m ? (float)(idx + 1u) : 0.0f;          // shifted labels: fg > 0 always

    int c = (t == 1) ? m : 0;
    sred[threadIdx.x] = c;
    __syncthreads();
    for (int s = 128; s > 0; s >>= 1) {
        if (threadIdx.x < s) sred[threadIdx.x] += sred[threadIdx.x + s];
        __syncthreads();
    }
    if (threadIdx.x == 0 && sred[0]) atomicAdd(&g_fgcount, sred[0]);
}

// ------------------------------------------------------------------
// fused k-iteration masked 3x3-max propagation, register-blocked + tile skipping.
// Tile 128x128, block (16,16)=256 threads, each thread an 8x8 patch.
// Horizontal neighbor exchange via warp shuffle (tx+-1 is in-warp).
// Vertical exchange via double-buffered sTV/sBV -> ONE barrier per iteration.
// Corners come from sTV/sBV of the diagonal threads.
__device__ __forceinline__ int sbase(int ty, int tx) {
    int tid = (ty << 4) + tx;
    return (tid << 3) + ((tid >> 2) << 2);   // 8-word slots + 4 pad per 4-thread group
}
__device__ __forceinline__ void hmax8(const float* s, float L, float R, float* o) {
    o[0] = fmaxf(fmaxf(L, s[0]), s[1]);
    #pragma unroll
    for (int j = 1; j < 7; j++) o[j] = fmaxf(fmaxf(s[j - 1], s[j]), s[j + 1]);
    o[7] = fmaxf(fmaxf(s[6], s[7]), R);
}

#define SXN 2304

__global__ __launch_bounds__(256, 2) void k_prop(int ab, int kIter) {
    __shared__ float sTV[2][SXN];   // top row (8 cols) per thread, double-buffered
    __shared__ float sBV[2][SXN];   // bottom row
    __shared__ int sRun;

    int tx = threadIdx.x;         // 0..15
    int ty = threadIdx.y;         // 0..15
    int bx = blockIdx.x, by = blockIdx.y, p = blockIdx.z;

    // ---- activity gate: 3x3 neighborhood of prev-launch flags ----
    if (tx == 0 && ty == 0) {
        const unsigned char* f = &g_flag[ab][p][by][bx];  // rows by..by+2, cols bx..bx+2
        int any = 0;
        #pragma unroll
        for (int dy = 0; dy < 3; dy++)
            any |= f[dy * 12 + 0] | f[dy * 12 + 1] | f[dy * 12 + 2];
        sRun = any;
    }
    __syncthreads();
    if (!sRun) {
        if (tx == 0 && ty == 0) g_flag[ab ^ 1][p][by + 1][bx + 1] = 0;
        return;   // buffers already equal here; dst holds current values
    }

    const float* __restrict__ src = ab ? g_labB : g_labA;
    float*       __restrict__ dst = ab ? g_labA : g_labB;

    int gx0 = bx * 112 - 8;
    int gy0 = by * 112 - 8;
    int gxb = gx0 + tx * 8;
    const float* __restrict__ sp = src + p * NPLANE;

    float v[8][8];
    bool colOK = ((unsigned)gxb < IMW);
    #pragma unroll
    for (int r = 0; r < 8; r++) {
        int gy = gy0 + ty * 8 + r;
        if (colOK && (unsigned)gy < IMH) {
            float4 a = *(const float4*)(sp + gy * IMW + gxb);
            float4 b = *(const float4*)(sp + gy * IMW + gxb + 4);
            v[r][0]=a.x; v[r][1]=a.y; v[r][2]=a.z; v[r][3]=a.w;
            v[r][4]=b.x; v[r][5]=b.y; v[r][6]=b.z; v[r][7]=b.w;
        } else {
            #pragma unroll
            for (int j = 0; j < 8; j++) v[r][j] = 0.0f;
        }
    }

    const int base = sbase(ty, tx);
    const int bU   = (ty > 0)  ? sbase(ty - 1, tx) : 0;
    const int bD   = (ty < 15) ? sbase(ty + 1, tx) : 0;
    const int bUL  = (ty > 0 && tx > 0)   ? sbase(ty - 1, tx - 1) : 0;
    const int bUR  = (ty > 0 && tx < 15)  ? sbase(ty - 1, tx + 1) : 0;
    const int bDL  = (ty < 15 && tx > 0)  ? sbase(ty + 1, tx - 1) : 0;
    const int bDR  = (ty < 15 && tx < 15) ? sbase(ty + 1, tx + 1) : 0;

    bool changed = false;
    bool tchanged = false;
    int par = 0;

    // prime vertical exchange buffer 0
    *(float4*)&sTV[0][base]     = make_float4(v[0][0], v[0][1], v[0][2], v[0][3]);
    *(float4*)&sTV[0][base + 4] = make_float4(v[0][4], v[0][5], v[0][6], v[0][7]);
    *(float4*)&sBV[0][base]     = make_float4(v[7][0], v[7][1], v[7][2], v[7][3]);
    *(float4*)&sBV[0][base + 4] = make_float4(v[7][4], v[7][5], v[7][6], v[7][7]);

    for (int it = 0; it < kIter; ++it) {
        int bc = __syncthreads_or((int)changed);   // visibility + convergence, ONE barrier
        if (it > 0 && !bc) break;
        changed = false;

        // ---- horizontal neighbors via warp shuffle (same warp: two 16-lane rows) ----
        float vl[8], vr[8];
        #pragma unroll
        for (int r = 0; r < 8; r++) {
            vl[r] = __shfl_up_sync(0xFFFFFFFFu, v[r][7], 1);    // left nb right edge
            vr[r] = __shfl_down_sync(0xFFFFFFFFu, v[r][0], 1);  // right nb left edge
        }
        if (tx == 0)  { 
            #pragma unroll
            for (int r = 0; r < 8; r++) vl[r] = 0.f; 
        }
        if (tx == 15) { 
            #pragma unroll
            for (int r = 0; r < 8; r++) vr[r] = 0.f; 
        }

        // ---- vertical neighbors + corners from shared buffer par ----
        float up[8], dn[8];
        float upL = 0.f, upR = 0.f, dnL = 0.f, dnR = 0.f;
        if (ty > 0) {
            float4 a = *(const float4*)&sBV[par][bU], c = *(const float4*)&sBV[par][bU + 4];
            up[0]=a.x; up[1]=a.y; up[2]=a.z; up[3]=a.w; up[4]=c.x; up[5]=c.y; up[6]=c.z; up[7]=c.w;
            if (tx > 0)  upL = sBV[par][bUL + 7];
            if (tx < 15) upR = sBV[par][bUR + 0];
        } else {
            #pragma unroll
            for (int j = 0; j < 8; j++) up[j] = 0.f;
        }
        if (ty < 15) {
            float4 a = *(const float4*)&sTV[par][bD], c = *(const float4*)&sTV[par][bD + 4];
            dn[0]=a.x; dn[1]=a.y; dn[2]=a.z; dn[3]=a.w; dn[4]=c.x; dn[5]=c.y; dn[6]=c.z; dn[7]=c.w;
            if (tx > 0)  dnL = sTV[par][bDL + 7];
            if (tx < 15) dnR = sTV[par][bDR + 0];
        } else {
            #pragma unroll
            for (int j = 0; j < 8; j++) dn[j] = 0.f;
        }

        // ---- rolling 3-row vertical combine over horizontal maxes (Jacobi) ----
        float rm[3][8];
        float dsum = 0.0f;                      // change detector on fma pipe
        hmax8(up,   upL,   upR,   rm[0]);
        hmax8(v[0], vl[0], vr[0], rm[1]);
        #pragma unroll
        for (int r = 0; r < 8; r++) {
            float* rmN = rm[(r + 2) % 3];
            if (r < 7) hmax8(v[r + 1], vl[r + 1], vr[r + 1], rmN);
            else       hmax8(dn, dnL, dnR, rmN);
            float* rmP = rm[r % 3];
            float* rmC = rm[(r + 1) % 3];
            #pragma unroll
            for (int j = 0; j < 8; j++) {
                float nv = fmaxf(fmaxf(rmP[j], rmC[j]), rmN[j]);
                nv = fminf(nv, v[r][j] * GATE);  // bg (0) stays 0, fg takes nv
                dsum += nv - v[r][j];            // nv >= v, exact (integer-valued floats)
                v[r][j] = nv;
            }
        }
        changed = (dsum > 0.0f);
        tchanged = tchanged || changed;

        // ---- publish updated edge rows into the OTHER buffer (no WAR hazard) ----
        if (it + 1 < kIter) {
            int np = par ^ 1;
            *(float4*)&sTV[np][base]     = make_float4(v[0][0], v[0][1], v[0][2], v[0][3]);
            *(float4*)&sTV[np][base + 4] = make_float4(v[0][4], v[0][5], v[0][6], v[0][7]);
            *(float4*)&sBV[np][base]     = make_float4(v[7][0], v[7][1], v[7][2], v[7][3]);
            *(float4*)&sBV[np][base + 4] = make_float4(v[7][4], v[7][5], v[7][6], v[7][7]);
        }
        par ^= 1;
    }

    // ---- store interior (8-ring halo dropped; 8-aligned segments) ----
    if (tx >= 1 && tx <= 14 && ty >= 1 && ty <= 14 && colOK) {
        float* __restrict__ dp = dst + p * NPLANE;
        #pragma unroll
        for (int r = 0; r < 8; r++) {
            int gy = gy0 + ty * 8 + r;
            if ((unsigned)gy < IMH) {
                *(float4*)(dp + gy * IMW + gxb)     = make_float4(v[r][0], v[r][1], v[r][2], v[r][3]);
                *(float4*)(dp + gy * IMW + gxb + 4) = make_float4(v[r][4], v[r][5], v[r][6], v[r][7]);
            }
        }
    }

    // publish activity flag for next launch
    int bc = __syncthreads_or((int)tchanged);
    if (tx == 0 && ty == 0) g_flag[ab ^ 1][p][by + 1][bx + 1] = bc ? 1 : 0;
}

// ---- mark distinct final values: bit[int(label)-1]; zero-flag for 0 ----
// g_labB is valid everywhere: tiles changing in the final launch were written to B;
// all other tiles have A==B (unchanged runs store values equal to their load).
__global__ void k_count() {
    int i = blockIdx.x * 256 + threadIdx.x;
    float v = g_labB[i];
    int t = i >> 22;
    if (v == 0.0f) {
        g_zeroflag[t] = 1;
    } else {
        float vp = __shfl_up_sync(0xFFFFFFFFu, v, 1);
        int lane = threadIdx.x & 31;
        if (lane == 0 || vp != v) {
            unsigned iv = (unsigned)v - 1u;
            atomicOr(&g_bitmap[t][iv >> 5], 1u << (iv & 31));
        }
    }
}

// ---- parallel popcount partial reduction ----
__global__ void k_fin1() {
    __shared__ int s0[256], s1[256];
    int tid = threadIdx.x;
    int c0 = 0, c1 = 0;
    for (int j = blockIdx.x * 256 + tid; j < NTENSOR / 32; j += gridDim.x * 256) {
        c0 += __popc(g_bitmap[0][j]);
        c1 += __popc(g_bitmap[1][j]);
    }
    s0[tid] = c0; s1[tid] = c1;
    __syncthreads();
    for (int s = 128; s > 0; s >>= 1) {
        if (tid < s) { s0[tid] += s0[tid + s]; s1[tid] += s1[tid + s]; }
        __syncthreads();
    }
    if (tid == 0) {
        if (s0[0]) atomicAdd(&g_cc[0], s0[0]);
        if (s1[0]) atomicAdd(&g_cc[1], s1[0]);
    }
}

// ---- emit scalar ----
__global__ void k_fin2(float* out) {
    float ccs  = (float)(g_cc[0] + g_zeroflag[0]);
    float ccsg = (float)(g_cc[1] + g_zeroflag[1]);
    float numSg = (float)g_fgcount;
    out[0] = fabsf(ccsg - ccs) / numSg;
}

// ------------------------------------------------------------------
extern "C" void kernel_launch(void* const* d_in, const int* in_sizes, int n_in,
                              void* d_out, int out_size) {
    const float* img = (const float*)d_in[0];
    const float* lab = (const float*)d_in[1];
    float* out = (float*)d_out;

    k_init<<<256, 256>>>();

    dim3 ob(32, 32), og(32, 32, 8);
    k_open<<<og, ob>>>(img, lab);

    k_thresh<<<NTOTAL / 256, 256>>>();

    dim3 pb(16, 16), pg(10, 10, 8);
    int ab = 0;
    for (int l = 0; l < 19; ++l) {
        int kI = (l < 18) ? 8 : 6;   // 18*8 + 6 = 150 iterations exactly
        k_prop<<<pg, pb>>>(ab, kI);
        ab ^= 1;
    }

    k_count<<<NTOTAL / 256, 256>>>();
    k_fin1<<<256, 256>>>();
    k_fin2<<<1, 1>>>(out);
}

// round 15
// speedup vs baseline: 1.7951x; 1.1794x over previous
#include <cuda_runtime.h>

#define IMH 1024
#define IMW 1024
#define NPLANE (IMH*IMW)          // 1048576
#define NTENSOR (4*NPLANE)        // 4194304
#define NTOTAL  (8*NPLANE)        // 8388608
#define BIGV 1e10f
#define GATE 1e30f

// ---- scratch (static device globals; no allocations anywhere) ----
__device__ float g_labA[NTOTAL];
__device__ float g_labB[NTOTAL];
__device__ unsigned int g_minmax[4];            // [img_min, img_max, lab_min, lab_max]
__device__ unsigned int g_bitmap[2][NTENSOR/32];// 2 x 524KB bit sets
__device__ int g_zeroflag[2];
__device__ int g_fgcount;
__device__ int g_cc[2];
// per-tile activity flags, ping-ponged by launch parity. [par][z][by+1][bx+1], 1-ring pad = 0.
__device__ unsigned char g_flag[2][8][12][12];

// ------------------------------------------------------------------
__global__ void k_init() {
    int i = blockIdx.x * blockDim.x + threadIdx.x;
    int total = 2 * (NTENSOR / 32);
    unsigned int* bm = &g_bitmap[0][0];
    for (int j = i; j < total; j += gridDim.x * blockDim.x) bm[j] = 0u;
    if (i < 2 * 8 * 12 * 12) ((unsigned char*)g_flag)[i] = 0;   // k_prop0 seeds parity-1 flags
    if (i == 0) {
        g_minmax[0] = 0xFFFFFFFFu; g_minmax[1] = 0u;
        g_minmax[2] = 0xFFFFFFFFu; g_minmax[3] = 0u;
        g_zeroflag[0] = 0; g_zeroflag[1] = 0;
        g_fgcount = 0;
        g_cc[0] = 0; g_cc[1] = 0;
    }
}

// ---- opening_cross (erosion then dilation, cross SE) + global min/max ----
__global__ __launch_bounds__(1024) void k_open(const float* __restrict__ img,
                                               const float* __restrict__ lab) {
    __shared__ float xs[36][37];
    __shared__ float er[34][35];
    __shared__ float smn[32], smx[32];

    int p = blockIdx.z;
    const float* src = (p < 4) ? (img + p * NPLANE) : (lab + (p - 4) * NPLANE);
    int x0 = blockIdx.x * 32, y0 = blockIdx.y * 32;
    int tx = threadIdx.x, ty = threadIdx.y;
    int tid = ty * 32 + tx;

    for (int i = tid; i < 36 * 36; i += 1024) {
        int yy = i / 36, xx = i % 36;
        int gy = y0 + yy - 2, gx = x0 + xx - 2;
        float v = BIGV;
        if ((unsigned)gy < IMH && (unsigned)gx < IMW) v = src[gy * IMW + gx];
        xs[yy][xx] = v;
    }
    __syncthreads();

    for (int i = tid; i < 34 * 34; i += 1024) {
        int yy = i / 34, xx = i % 34;
        int gy = y0 + yy - 1, gx = x0 + xx - 1;
        float e;
        if ((unsigned)gy < IMH && (unsigned)gx < IMW) {
            e = xs[yy + 1][xx + 1];
            e = fminf(e, xs[yy][xx + 1]);
            e = fminf(e, xs[yy + 2][xx + 1]);
            e = fminf(e, xs[yy + 1][xx]);
            e = fminf(e, xs[yy + 1][xx + 2]);
        } else {
            e = -BIGV;
        }
        er[yy][xx] = e;
    }
    __syncthreads();

    float o = er[ty + 1][tx + 1];
    o = fmaxf(o, er[ty][tx + 1]);
    o = fmaxf(o, er[ty + 2][tx + 1]);
    o = fmaxf(o, er[ty + 1][tx]);
    o = fmaxf(o, er[ty + 1][tx + 2]);
    g_labA[p * NPLANE + (y0 + ty) * IMW + (x0 + tx)] = o;

    float wm = o, wx = o;
    #pragma unroll
    for (int s = 16; s > 0; s >>= 1) {
        wm = fminf(wm, __shfl_xor_sync(0xFFFFFFFFu, wm, s));
        wx = fmaxf(wx, __shfl_xor_sync(0xFFFFFFFFu, wx, s));
    }
    int wid = tid >> 5, lane = tid & 31;
    if (lane == 0) { smn[wid] = wm; smx[wid] = wx; }
    __syncthreads();
    if (wid == 0) {
        wm = smn[lane]; wx = smx[lane];
        #pragma unroll
        for (int s = 16; s > 0; s >>= 1) {
            wm = fminf(wm, __shfl_xor_sync(0xFFFFFFFFu, wm, s));
            wx = fmaxf(wx, __shfl_xor_sync(0xFFFFFFFFu, wx, s));
        }
        if (lane == 0) {
            int t = p >> 2;
            atomicMin(&g_minmax[t * 2 + 0], __float_as_uint(wm));
            atomicMax(&g_minmax[t * 2 + 1], __float_as_uint(wx));
        }
    }
}

// ------------------------------------------------------------------
// shared helpers for the propagation kernels
__device__ __forceinline__ int sbase(int ty, int tx) {
    int tid = (ty << 4) + tx;
    return (tid << 3) + ((tid >> 2) << 2);   // 8-word slots + 4 pad per 4-thread group
}
__device__ __forceinline__ void hmax8(const float* s, float L, float R, float* o) {
    o[0] = fmaxf(fmaxf(L, s[0]), s[1]);
    #pragma unroll
    for (int j = 1; j < 7; j++) o[j] = fmaxf(fmaxf(s[j - 1], s[j]), s[j + 1]);
    o[7] = fmaxf(fmaxf(s[6], s[7]), R);
}

#define SXN 2304

// Iteration engine: kIter Jacobi steps on the register tile with shuffle
// horizontal exchange and double-buffered shared vertical exchange.
// Returns whether anything changed.
__device__ __forceinline__ bool prop_iterate(
    float v[8][8], int tx, int ty, int kIter,
    float sTV[2][SXN], float sBV[2][SXN])
{
    const int base = sbase(ty, tx);
    const int bU   = (ty > 0)  ? sbase(ty - 1, tx) : 0;
    const int bD   = (ty < 15) ? sbase(ty + 1, tx) : 0;
    const int bUL  = (ty > 0 && tx > 0)   ? sbase(ty - 1, tx - 1) : 0;
    const int bUR  = (ty > 0 && tx < 15)  ? sbase(ty - 1, tx + 1) : 0;
    const int bDL  = (ty < 15 && tx > 0)  ? sbase(ty + 1, tx - 1) : 0;
    const int bDR  = (ty < 15 && tx < 15) ? sbase(ty + 1, tx + 1) : 0;

    bool changed = false;
    bool tchanged = false;
    int par = 0;

    *(float4*)&sTV[0][base]     = make_float4(v[0][0], v[0][1], v[0][2], v[0][3]);
    *(float4*)&sTV[0][base + 4] = make_float4(v[0][4], v[0][5], v[0][6], v[0][7]);
    *(float4*)&sBV[0][base]     = make_float4(v[7][0], v[7][1], v[7][2], v[7][3]);
    *(float4*)&sBV[0][base + 4] = make_float4(v[7][4], v[7][5], v[7][6], v[7][7]);

    for (int it = 0; it < kIter; ++it) {
        int bc = __syncthreads_or((int)changed);   // visibility + convergence, ONE barrier
        if (it > 0 && !bc) break;
        changed = false;

        float vl[8], vr[8];
        #pragma unroll
        for (int r = 0; r < 8; r++) {
            vl[r] = __shfl_up_sync(0xFFFFFFFFu, v[r][7], 1);
            vr[r] = __shfl_down_sync(0xFFFFFFFFu, v[r][0], 1);
        }
        if (tx == 0) {
            #pragma unroll
            for (int r = 0; r < 8; r++) vl[r] = 0.f;
        }
        if (tx == 15) {
            #pragma unroll
            for (int r = 0; r < 8; r++) vr[r] = 0.f;
        }

        float up[8], dn[8];
        float upL = 0.f, upR = 0.f, dnL = 0.f, dnR = 0.f;
        if (ty > 0) {
            float4 a = *(const float4*)&sBV[par][bU], c = *(const float4*)&sBV[par][bU + 4];
            up[0]=a.x; up[1]=a.y; up[2]=a.z; up[3]=a.w; up[4]=c.x; up[5]=c.y; up[6]=c.z; up[7]=c.w;
            if (tx > 0)  upL = sBV[par][bUL + 7];
            if (tx < 15) upR = sBV[par][bUR + 0];
        } else {
            #pragma unroll
            for (int j = 0; j < 8; j++) up[j] = 0.f;
        }
        if (ty < 15) {
            float4 a = *(const float4*)&sTV[par][bD], c = *(const float4*)&sTV[par][bD + 4];
            dn[0]=a.x; dn[1]=a.y; dn[2]=a.z; dn[3]=a.w; dn[4]=c.x; dn[5]=c.y; dn[6]=c.z; dn[7]=c.w;
            if (tx > 0)  dnL = sTV[par][bDL + 7];
            if (tx < 15) dnR = sTV[par][bDR + 0];
        } else {
            #pragma unroll
            for (int j = 0; j < 8; j++) dn[j] = 0.f;
        }

        float rm[3][8];
        float dsum = 0.0f;
        hmax8(up,   upL,   upR,   rm[0]);
        hmax8(v[0], vl[0], vr[0], rm[1]);
        #pragma unroll
        for (int r = 0; r < 8; r++) {
            float* rmN = rm[(r + 2) % 3];
            if (r < 7) hmax8(v[r + 1], vl[r + 1], vr[r + 1], rmN);
            else       hmax8(dn, dnL, dnR, rmN);
            float* rmP = rm[r % 3];
            float* rmC = rm[(r + 1) % 3];
            #pragma unroll
            for (int j = 0; j < 8; j++) {
                float nv = fmaxf(fmaxf(rmP[j], rmC[j]), rmN[j]);
                nv = fminf(nv, v[r][j] * GATE);  // bg (0) stays 0, fg takes nv
                dsum += nv - v[r][j];            // nv >= v, exact (integer-valued floats)
                v[r][j] = nv;
            }
        }
        changed = (dsum > 0.0f);
        tchanged = tchanged || changed;

        if (it + 1 < kIter) {
            int np = par ^ 1;
            *(float4*)&sTV[np][base]     = make_float4(v[0][0], v[0][1], v[0][2], v[0][3]);
            *(float4*)&sTV[np][base + 4] = make_float4(v[0][4], v[0][5], v[0][6], v[0][7]);
            *(float4*)&sBV[np][base]     = make_float4(v[7][0], v[7][1], v[7][2], v[7][3]);
            *(float4*)&sBV[np][base + 4] = make_float4(v[7][4], v[7][5], v[7][6], v[7][7]);
        }
        par ^= 1;
    }
    return tchanged;
}

// ------------------------------------------------------------------
// Launch 0: fused threshold+labelize (reads opened values from A), fg count,
// 8 propagation iterations, store B. Publishes flag=1 so launch 1 runs ALL
// tiles (launch 1 writes A everywhere, restoring the A==B skip invariant).
__global__ __launch_bounds__(256, 2) void k_prop0() {
    __shared__ float sTV[2][SXN];
    __shared__ float sBV[2][SXN];
    __shared__ int swr[8];

    int tx = threadIdx.x;         // 0..15
    int ty = threadIdx.y;         // 0..15
    int bx = blockIdx.x, by = blockIdx.y, p = blockIdx.z;
    int tid = ty * 16 + tx;

    int gx0 = bx * 112 - 8;
    int gy0 = by * 112 - 8;
    int gxb = gx0 + tx * 8;
    const float* __restrict__ sp = g_labA + p * NPLANE;

    int t = p >> 2;
    float mn  = __uint_as_float(g_minmax[t * 2 + 0]);
    float rng = __uint_as_float(g_minmax[t * 2 + 1]) - mn + 1e-10f;
    unsigned lbase = (unsigned)((p & 3) * NPLANE) + 1u;     // label = idx+1

    float v[8][8];
    bool colOK = ((unsigned)gxb < IMW);
    bool countable = (p >= 4 && tx >= 1 && tx <= 14 && ty >= 1 && ty <= 14);
    int cnt = 0;
    #pragma unroll
    for (int r = 0; r < 8; r++) {
        int gy = gy0 + ty * 8 + r;
        if (colOK && (unsigned)gy < IMH) {
            float4 a = *(const float4*)(sp + gy * IMW + gxb);
            float4 b = *(const float4*)(sp + gy * IMW + gxb + 4);
            float o[8] = {a.x, a.y, a.z, a.w, b.x, b.y, b.z, b.w};
            unsigned rowb = lbase + (unsigned)(gy * IMW + gxb);
            int rc = 0;
            #pragma unroll
            for (int j = 0; j < 8; j++) {
                float nrm = __fdiv_rn(o[j] - mn, rng);       // IEEE div, matches XLA
                int m = (nrm >= 0.5f) ? 1 : 0;
                v[r][j] = m ? (float)(rowb + (unsigned)j) : 0.0f;
                rc += m;
            }
            if (countable) cnt += rc;
        } else {
            #pragma unroll
            for (int j = 0; j < 8; j++) v[r][j] = 0.0f;
        }
    }

    // fg count: warp + block reduce, one atomic per block
    #pragma unroll
    for (int s = 16; s > 0; s >>= 1) cnt += __shfl_xor_sync(0xFFFFFFFFu, cnt, s);
    int wid = tid >> 5, lane = tid & 31;
    if (lane == 0) swr[wid] = cnt;
    __syncthreads();
    if (tid == 0) {
        int tot = 0;
        #pragma unroll
        for (int w = 0; w < 8; w++) tot += swr[w];
        if (tot) atomicAdd(&g_fgcount, tot);
    }

    prop_iterate(v, tx, ty, 8, sTV, sBV);

    // store interior to B
    if (tx >= 1 && tx <= 14 && ty >= 1 && ty <= 14 && colOK) {
        float* __restrict__ dp = g_labB + p * NPLANE;
        #pragma unroll
        for (int r = 0; r < 8; r++) {
            int gy = gy0 + ty * 8 + r;
            if ((unsigned)gy < IMH) {
                *(float4*)(dp + gy * IMW + gxb)     = make_float4(v[r][0], v[r][1], v[r][2], v[r][3]);
                *(float4*)(dp + gy * IMW + gxb + 4) = make_float4(v[r][4], v[r][5], v[r][6], v[r][7]);
            }
        }
    }

    // force launch 1 to run everywhere (writes A everywhere -> invariant holds after)
    if (tx == 0 && ty == 0) g_flag[1][p][by + 1][bx + 1] = 1;
}

// ------------------------------------------------------------------
// Launches 1..18: identical hot path to the verified R14 kernel.
__global__ __launch_bounds__(256, 2) void k_prop(int ab, int kIter) {
    __shared__ float sTV[2][SXN];
    __shared__ float sBV[2][SXN];
    __shared__ int sRun;

    int tx = threadIdx.x;         // 0..15
    int ty = threadIdx.y;         // 0..15
    int bx = blockIdx.x, by = blockIdx.y, p = blockIdx.z;

    // ---- activity gate: 3x3 neighborhood of prev-launch flags ----
    if (tx == 0 && ty == 0) {
        const unsigned char* f = &g_flag[ab][p][by][bx];  // rows by..by+2, cols bx..bx+2
        int any = 0;
        #pragma unroll
        for (int dy = 0; dy < 3; dy++)
            any |= f[dy * 12 + 0] | f[dy * 12 + 1] | f[dy * 12 + 2];
        sRun = any;
    }
    __syncthreads();
    if (!sRun) {
        if (tx == 0 && ty == 0) g_flag[ab ^ 1][p][by + 1][bx + 1] = 0;
        return;   // buffers already equal here; dst holds current values
    }

    const float* __restrict__ src = ab ? g_labB : g_labA;
    float*       __restrict__ dst = ab ? g_labA : g_labB;

    int gx0 = bx * 112 - 8;
    int gy0 = by * 112 - 8;
    int gxb = gx0 + tx * 8;
    const float* __restrict__ sp = src + p * NPLANE;

    float v[8][8];
    bool colOK = ((unsigned)gxb < IMW);
    #pragma unroll
    for (int r = 0; r < 8; r++) {
        int gy = gy0 + ty * 8 + r;
        if (colOK && (unsigned)gy < IMH) {
            float4 a = *(const float4*)(sp + gy * IMW + gxb);
            float4 b = *(const float4*)(sp + gy * IMW + gxb + 4);
            v[r][0]=a.x; v[r][1]=a.y; v[r][2]=a.z; v[r][3]=a.w;
            v[r][4]=b.x; v[r][5]=b.y; v[r][6]=b.z; v[r][7]=b.w;
        } else {
            #pragma unroll
            for (int j = 0; j < 8; j++) v[r][j] = 0.0f;
        }
    }

    bool tchanged = prop_iterate(v, tx, ty, kIter, sTV, sBV);

    // store interior (8-ring halo dropped; 8-aligned segments)
    if (tx >= 1 && tx <= 14 && ty >= 1 && ty <= 14 && colOK) {
        float* __restrict__ dp = dst + p * NPLANE;
        #pragma unroll
        for (int r = 0; r < 8; r++) {
            int gy = gy0 + ty * 8 + r;
            if ((unsigned)gy < IMH) {
                *(float4*)(dp + gy * IMW + gxb)     = make_float4(v[r][0], v[r][1], v[r][2], v[r][3]);
                *(float4*)(dp + gy * IMW + gxb + 4) = make_float4(v[r][4], v[r][5], v[r][6], v[r][7]);
            }
        }
    }

    // publish activity flag for next launch
    int bc = __syncthreads_or((int)tchanged);
    if (tx == 0 && ty == 0) g_flag[ab ^ 1][p][by + 1][bx + 1] = bc ? 1 : 0;
}

// ---- mark distinct final values (4 px/thread): bit[int(label)-1]; zero-flag for 0 ----
__global__ void k_count() {
    int i4 = blockIdx.x * 256 + threadIdx.x;
    uint4 q = ((const uint4*)g_labB)[i4];
    int t = (i4 * 4) >> 22;
    unsigned vals[4] = {q.x, q.y, q.z, q.w};
    unsigned prev = __shfl_up_sync(0xFFFFFFFFu, q.w, 1);
    int lane = threadIdx.x & 31;
    bool zf = false;
    #pragma unroll
    for (int j = 0; j < 4; j++) {
        unsigned u = vals[j];
        if (u == 0u) {
            zf = true;
        } else if ((j == 0 && lane == 0) || u != prev) {
            unsigned iv = (unsigned)__uint_as_float(u) - 1u;
            atomicOr(&g_bitmap[t][iv >> 5], 1u << (iv & 31));
        }
        prev = u;
    }
    if (zf) g_zeroflag[t] = 1;
}

// ---- parallel popcount partial reduction ----
__global__ void k_fin1() {
    __shared__ int s0[256], s1[256];
    int tid = threadIdx.x;
    int c0 = 0, c1 = 0;
    for (int j = blockIdx.x * 256 + tid; j < NTENSOR / 32; j += gridDim.x * 256) {
        c0 += __popc(g_bitmap[0][j]);
        c1 += __popc(g_bitmap[1][j]);
    }
    s0[tid] = c0; s1[tid] = c1;
    __syncthreads();
    for (int s = 128; s > 0; s >>= 1) {
        if (tid < s) { s0[tid] += s0[tid + s]; s1[tid] += s1[tid + s]; }
        __syncthreads();
    }
    if (tid == 0) {
        if (s0[0]) atomicAdd(&g_cc[0], s0[0]);
        if (s1[0]) atomicAdd(&g_cc[1], s1[0]);
    }
}

// ---- emit scalar ----
__global__ void k_fin2(float* out) {
    float ccs  = (float)(g_cc[0] + g_zeroflag[0]);
    float ccsg = (float)(g_cc[1] + g_zeroflag[1]);
    float numSg = (float)g_fgcount;
    out[0] = fabsf(ccsg - ccs) / numSg;
}

// ------------------------------------------------------------------
extern "C" void kernel_launch(void* const* d_in, const int* in_sizes, int n_in,
                              void* d_out, int out_size) {
    const float* img = (const float*)d_in[0];
    const float* lab = (const float*)d_in[1];
    float* out = (float*)d_out;

    k_init<<<256, 256>>>();

    dim3 ob(32, 32), og(32, 32, 8);
    k_open<<<og, ob>>>(img, lab);

    dim3 pb(16, 16), pg(10, 10, 8);
    k_prop0<<<pg, pb>>>();                 // launch 0: fused threshold + 8 iters (A -> B)
    for (int l = 1; l < 19; ++l) {
        int kI = (l < 18) ? 8 : 6;         // 8 + 17*8 + 6 = 150 iterations exactly
        k_prop<<<pg, pb>>>(l & 1, kI);
    }
    // final labels land in g_labB (launch 18 has ab=0, writes B)

    k_count<<<NTOTAL / 1024, 256>>>();
    k_fin1<<<256, 256>>>();
    k_fin2<<<1, 1>>>(out);
}